// round 8
// baseline (speedup 1.0000x reference)
#include <cuda_runtime.h>

#define NA 3
#define NC 80
#define HH 76
#define WW 76
#define HW (HH * WW)                 /* 5776 */
#define NPLANES (16 * NA)            /* 48 = B*A planes */
#define TOTAL (NPLANES * HW)         /* 277248 */
#define BOXES_ELEMS (TOTAL * 4)
#define BLKS_PER_PLANE 91            /* ceil(5776/64) */
#define THREADS 256
#define CONF_STRIDE 85               /* odd -> conflict-free column STS */
#define RED_STRIDE 5

__global__ __launch_bounds__(THREADS, 6) void yolo_decode_kernel(
    const float* __restrict__ in, float* __restrict__ out)
{
    __shared__ float conf_s[64 * CONF_STRIDE];   // 64 rows x 80 (padded to 85)
    __shared__ float red_max[64 * RED_STRIDE];   // [row][w<4]=partial max, [4]=det
    __shared__ float red_sum[64 * RED_STRIDE];   // [row][w<4]=partial expsum
    __shared__ float box_s[64 * RED_STRIDE];     // [row][comp<4]

    const int tid  = threadIdx.x;
    const int w    = (tid >> 5) & 3;     // warp within group: owns classes 4i+w
    const int s    = tid >> 7;           // group 0/1 (32 positions each)
    const int lane = tid & 31;

    const int plane = blockIdx.x / BLKS_PER_PLANE;             // = b*NA + a
    const int blk   = blockIdx.x - plane * BLKS_PER_PLANE;
    const int a     = plane % NA;

    const int pos_base = blk * 64;
    const int r   = s * 32 + lane;       // row within CTA (0..63)
    const int pos = pos_base + r;
    const bool valid = pos < HW;

    const float* __restrict__ p = in + (size_t)plane * (5 + NC) * HW + pos;

    // ---- 20 class logits per thread; each warp LDG = 32 consecutive pos = full line(s)
    float cls[20];
    float m = -1e30f;
    if (valid) {
#pragma unroll
        for (int i = 0; i < 20; i++) cls[i] = p[(5 + 4 * i + w) * HW];
#pragma unroll
        for (int i = 0; i < 20; i++) m = fmaxf(m, cls[i]);
    }
    red_max[r * RED_STRIDE + w] = m;

    // ---- head channel w -> box component w; warp 0 also does det-conf (ch 4)
    if (valid) {
        const float awW[NA] = {1.5f / WW, 2.375f / WW, 5.0f / WW};
        const float ahH[NA] = {2.0f / HH, 4.5f  / HH, 3.5f / HH};
        float t = p[w * HW];
        float comp;
        if (w == 0)
            comp = (__fdividef(1.f, 1.f + __expf(-t)) + (float)(pos % WW)) * (1.0f / WW);
        else if (w == 1)
            comp = (__fdividef(1.f, 1.f + __expf(-t)) + (float)(pos / WW)) * (1.0f / HH);
        else if (w == 2)
            comp = __expf(t) * awW[a];
        else
            comp = __expf(t) * ahH[a];
        box_s[r * RED_STRIDE + w] = comp;
        if (w == 0) {
            float tc = p[4 * HW];
            red_max[r * RED_STRIDE + 4] = __fdividef(1.f, 1.f + __expf(-tc));
        }
    }
    __syncthreads();

    // ---- global max over the 4 partials, exp + partial sum
    float gm = fmaxf(fmaxf(red_max[r * RED_STRIDE + 0], red_max[r * RED_STRIDE + 1]),
                     fmaxf(red_max[r * RED_STRIDE + 2], red_max[r * RED_STRIDE + 3]));
    float ssum = 0.f;
    if (valid) {
#pragma unroll
        for (int i = 0; i < 20; i++) {
            cls[i] = __expf(cls[i] - gm);
            ssum += cls[i];
        }
    }
    red_sum[r * RED_STRIDE + w] = ssum;
    __syncthreads();

    // ---- scale = det / sum, stage conf row (conflict-free: 85r + 4i + w)
    if (valid) {
        float tot = red_sum[r * RED_STRIDE + 0] + red_sum[r * RED_STRIDE + 1] +
                    red_sum[r * RED_STRIDE + 2] + red_sum[r * RED_STRIDE + 3];
        float scale = __fdividef(red_max[r * RED_STRIDE + 4], tot);
#pragma unroll
        for (int i = 0; i < 20; i++)
            conf_s[r * CONF_STRIDE + 4 * i + w] = cls[i] * scale;
    }
    __syncthreads();

    // ---- cooperative copy-out
    const int valid_rows = min(64, HW - pos_base);

    // boxes: assemble float4 per row
    if (tid < valid_rows) {
        float4 b = make_float4(box_s[tid * RED_STRIDE + 0],
                               box_s[tid * RED_STRIDE + 1],
                               box_s[tid * RED_STRIDE + 2],
                               box_s[tid * RED_STRIDE + 3]);
        ((float4*)out)[(size_t)plane * HW + pos_base + tid] = b;
    }

    // confs: 64*80 floats, consecutive threads -> consecutive addresses
    float* __restrict__ dst = out + (size_t)BOXES_ELEMS
                            + ((size_t)plane * HW + pos_base) * NC;
    const unsigned nk = (unsigned)valid_rows * NC;
#pragma unroll
    for (int j = 0; j < 20; j++) {
        unsigned k = tid + j * THREADS;          // 0..5119
        if (k < nk) {
            unsigned rr = k / NC;
            unsigned cc = k - rr * NC;
            dst[k] = conf_s[rr * CONF_STRIDE + cc];
        }
    }
}

extern "C" void kernel_launch(void* const* d_in, const int* in_sizes, int n_in,
                              void* d_out, int out_size)
{
    const float* in = (const float*)d_in[0];
    float* out = (float*)d_out;
    yolo_decode_kernel<<<NPLANES * BLKS_PER_PLANE, THREADS>>>(in, out);
}

// round 9
// speedup vs baseline: 1.0052x; 1.0052x over previous
#include <cuda_runtime.h>

#define NA 3
#define NC 80
#define HH 76
#define WW 76
#define HW (HH * WW)                 /* 5776 */
#define NPLANES (16 * NA)            /* 48 = B*A planes */
#define TOTAL (NPLANES * HW)         /* 277248 */
#define BOXES_ELEMS (TOTAL * 4)
#define BLKS_PER_PLANE 91            /* ceil(5776/64) */
#define THREADS 256
#define CONF_STRIDE 85               /* odd -> conflict-free column STS */
#define RED_STRIDE 5

__global__ __launch_bounds__(THREADS, 6) void yolo_decode_kernel(
    const float* __restrict__ in, float* __restrict__ out)
{
    __shared__ float conf_s[64 * CONF_STRIDE];   // 64 rows x 80 (padded to 85)
    __shared__ float red_max[64 * RED_STRIDE];   // [row][w<4]=partial max, [4]=det
    __shared__ float red_sum[64 * RED_STRIDE];   // [row][w<4]=partial expsum
    __shared__ float box_s[64 * RED_STRIDE];     // [row][comp<4]

    const int tid  = threadIdx.x;
    const int w    = (tid >> 5) & 3;     // warp within group: owns classes 4i+w
    const int s    = tid >> 7;           // group 0/1 (32 positions each)
    const int lane = tid & 31;

    const int plane = blockIdx.x / BLKS_PER_PLANE;             // = b*NA + a
    const int blk   = blockIdx.x - plane * BLKS_PER_PLANE;
    const int a     = plane % NA;

    const int pos_base = blk * 64;
    const int r   = s * 32 + lane;       // row within CTA (0..63)
    const int pos = pos_base + r;
    const bool valid = pos < HW;

    const float* __restrict__ p = in + (size_t)plane * (5 + NC) * HW + pos;

    // ---- 20 class logits per thread; each warp LDG = 32 consecutive pos = full line(s)
    float cls[20];
    float m = -1e30f;
    if (valid) {
#pragma unroll
        for (int i = 0; i < 20; i++) cls[i] = p[(5 + 4 * i + w) * HW];
#pragma unroll
        for (int i = 0; i < 20; i++) m = fmaxf(m, cls[i]);
    }
    red_max[r * RED_STRIDE + w] = m;

    // ---- head channel w -> box component w; warp 0 also does det-conf (ch 4)
    if (valid) {
        const float awW[NA] = {1.5f / WW, 2.375f / WW, 5.0f / WW};
        const float ahH[NA] = {2.0f / HH, 4.5f  / HH, 3.5f / HH};
        float t = p[w * HW];
        float comp;
        if (w == 0)
            comp = (__fdividef(1.f, 1.f + __expf(-t)) + (float)(pos % WW)) * (1.0f / WW);
        else if (w == 1)
            comp = (__fdividef(1.f, 1.f + __expf(-t)) + (float)(pos / WW)) * (1.0f / HH);
        else if (w == 2)
            comp = __expf(t) * awW[a];
        else
            comp = __expf(t) * ahH[a];
        box_s[r * RED_STRIDE + w] = comp;
        if (w == 0) {
            float tc = p[4 * HW];
            red_max[r * RED_STRIDE + 4] = __fdividef(1.f, 1.f + __expf(-tc));
        }
    }
    __syncthreads();

    // ---- global max over the 4 partials, exp + partial sum
    float gm = fmaxf(fmaxf(red_max[r * RED_STRIDE + 0], red_max[r * RED_STRIDE + 1]),
                     fmaxf(red_max[r * RED_STRIDE + 2], red_max[r * RED_STRIDE + 3]));
    float ssum = 0.f;
    if (valid) {
#pragma unroll
        for (int i = 0; i < 20; i++) {
            cls[i] = __expf(cls[i] - gm);
            ssum += cls[i];
        }
    }
    red_sum[r * RED_STRIDE + w] = ssum;
    __syncthreads();

    // ---- scale = det / sum, stage conf row (conflict-free: 85r + 4i + w)
    if (valid) {
        float tot = red_sum[r * RED_STRIDE + 0] + red_sum[r * RED_STRIDE + 1] +
                    red_sum[r * RED_STRIDE + 2] + red_sum[r * RED_STRIDE + 3];
        float scale = __fdividef(red_max[r * RED_STRIDE + 4], tot);
#pragma unroll
        for (int i = 0; i < 20; i++)
            conf_s[r * CONF_STRIDE + 4 * i + w] = cls[i] * scale;
    }
    __syncthreads();

    // ---- cooperative copy-out
    const int valid_rows = min(64, HW - pos_base);

    // boxes: assemble float4 per row
    if (tid < valid_rows) {
        float4 b = make_float4(box_s[tid * RED_STRIDE + 0],
                               box_s[tid * RED_STRIDE + 1],
                               box_s[tid * RED_STRIDE + 2],
                               box_s[tid * RED_STRIDE + 3]);
        ((float4*)out)[(size_t)plane * HW + pos_base + tid] = b;
    }

    // confs: 64*80 floats, consecutive threads -> consecutive addresses
    float* __restrict__ dst = out + (size_t)BOXES_ELEMS
                            + ((size_t)plane * HW + pos_base) * NC;
    const unsigned nk = (unsigned)valid_rows * NC;
#pragma unroll
    for (int j = 0; j < 20; j++) {
        unsigned k = tid + j * THREADS;          // 0..5119
        if (k < nk) {
            unsigned rr = k / NC;
            unsigned cc = k - rr * NC;
            dst[k] = conf_s[rr * CONF_STRIDE + cc];
        }
    }
}

extern "C" void kernel_launch(void* const* d_in, const int* in_sizes, int n_in,
                              void* d_out, int out_size)
{
    const float* in = (const float*)d_in[0];
    float* out = (float*)d_out;
    yolo_decode_kernel<<<NPLANES * BLKS_PER_PLANE, THREADS>>>(in, out);
}

// round 10
// speedup vs baseline: 1.0363x; 1.0309x over previous
#include <cuda_runtime.h>

#define NA 3
#define NC 80
#define HH 76
#define WW 76
#define HW (HH * WW)                 /* 5776 */
#define NPLANES (16 * NA)            /* 48 = B*A planes */
#define TOTAL (NPLANES * HW)         /* 277248 */
#define BOXES_ELEMS (TOTAL * 4)
#define BLKS_PER_PLANE 91            /* ceil(5776/64) */
#define THREADS 256
#define CONF_STRIDE 85               /* odd -> conflict-free column STS */
#define RED_STRIDE 5

__global__ __launch_bounds__(THREADS, 6) void yolo_decode_kernel(
    const float* __restrict__ in, float* __restrict__ out)
{
    __shared__ float conf_s[64 * CONF_STRIDE];   // 64 rows x 80 (padded to 85)
    __shared__ float red_max[64 * RED_STRIDE];   // [row][w<4]=partial max, [4]=det
    __shared__ float red_sum[64 * RED_STRIDE];   // [row][w<4]=partial expsum
    __shared__ float box_s[64 * RED_STRIDE];     // [row][comp<4]

    const int tid  = threadIdx.x;
    const int w    = (tid >> 5) & 3;     // warp within group: owns classes 4i+w
    const int s    = tid >> 7;           // group 0/1 (32 positions each)
    const int lane = tid & 31;

    const int plane = blockIdx.x / BLKS_PER_PLANE;             // = b*NA + a
    const int blk   = blockIdx.x - plane * BLKS_PER_PLANE;
    const int a     = plane % NA;

    const int pos_base = blk * 64;
    const int r   = s * 32 + lane;       // row within CTA (0..63)
    const int pos = pos_base + r;
    const bool valid = pos < HW;

    const float* __restrict__ p = in + (size_t)plane * (5 + NC) * HW + pos;

    // ---- 20 class logits per thread; each warp LDG = 32 consecutive pos = full line(s)
    float cls[20];
    float m = -1e30f;
    if (valid) {
#pragma unroll
        for (int i = 0; i < 20; i++) cls[i] = p[(5 + 4 * i + w) * HW];
#pragma unroll
        for (int i = 0; i < 20; i++) m = fmaxf(m, cls[i]);
    }
    red_max[r * RED_STRIDE + w] = m;

    // ---- head channel w -> box component w; warp 0 also does det-conf (ch 4)
    if (valid) {
        const float awW[NA] = {1.5f / WW, 2.375f / WW, 5.0f / WW};
        const float ahH[NA] = {2.0f / HH, 4.5f  / HH, 3.5f / HH};
        float t = p[w * HW];
        float comp;
        if (w == 0)
            comp = (__fdividef(1.f, 1.f + __expf(-t)) + (float)(pos % WW)) * (1.0f / WW);
        else if (w == 1)
            comp = (__fdividef(1.f, 1.f + __expf(-t)) + (float)(pos / WW)) * (1.0f / HH);
        else if (w == 2)
            comp = __expf(t) * awW[a];
        else
            comp = __expf(t) * ahH[a];
        box_s[r * RED_STRIDE + w] = comp;
        if (w == 0) {
            float tc = p[4 * HW];
            red_max[r * RED_STRIDE + 4] = __fdividef(1.f, 1.f + __expf(-tc));
        }
    }
    __syncthreads();

    // ---- global max over the 4 partials, exp + partial sum
    float gm = fmaxf(fmaxf(red_max[r * RED_STRIDE + 0], red_max[r * RED_STRIDE + 1]),
                     fmaxf(red_max[r * RED_STRIDE + 2], red_max[r * RED_STRIDE + 3]));
    float ssum = 0.f;
    if (valid) {
#pragma unroll
        for (int i = 0; i < 20; i++) {
            cls[i] = __expf(cls[i] - gm);
            ssum += cls[i];
        }
    }
    red_sum[r * RED_STRIDE + w] = ssum;
    __syncthreads();

    // ---- scale = det / sum, stage conf row (conflict-free: 85r + 4i + w)
    if (valid) {
        float tot = red_sum[r * RED_STRIDE + 0] + red_sum[r * RED_STRIDE + 1] +
                    red_sum[r * RED_STRIDE + 2] + red_sum[r * RED_STRIDE + 3];
        float scale = __fdividef(red_max[r * RED_STRIDE + 4], tot);
#pragma unroll
        for (int i = 0; i < 20; i++)
            conf_s[r * CONF_STRIDE + 4 * i + w] = cls[i] * scale;
    }
    __syncthreads();

    // ---- cooperative copy-out
    const int valid_rows = min(64, HW - pos_base);

    // boxes: assemble float4 per row
    if (tid < valid_rows) {
        float4 b = make_float4(box_s[tid * RED_STRIDE + 0],
                               box_s[tid * RED_STRIDE + 1],
                               box_s[tid * RED_STRIDE + 2],
                               box_s[tid * RED_STRIDE + 3]);
        ((float4*)out)[(size_t)plane * HW + pos_base + tid] = b;
    }

    // confs: 64*80 floats, consecutive threads -> consecutive addresses
    float* __restrict__ dst = out + (size_t)BOXES_ELEMS
                            + ((size_t)plane * HW + pos_base) * NC;
    const unsigned nk = (unsigned)valid_rows * NC;
#pragma unroll
    for (int j = 0; j < 20; j++) {
        unsigned k = tid + j * THREADS;          // 0..5119
        if (k < nk) {
            unsigned rr = k / NC;
            unsigned cc = k - rr * NC;
            dst[k] = conf_s[rr * CONF_STRIDE + cc];
        }
    }
}

extern "C" void kernel_launch(void* const* d_in, const int* in_sizes, int n_in,
                              void* d_out, int out_size)
{
    const float* in = (const float*)d_in[0];
    float* out = (float*)d_out;
    yolo_decode_kernel<<<NPLANES * BLKS_PER_PLANE, THREADS>>>(in, out);
}